// round 4
// baseline (speedup 1.0000x reference)
#include <cuda_runtime.h>
#include <cstdint>

#define N_NODES 100000
#define N_EDGES 800000
#define N_GRAPHS 128

// ---------------- scratch (device globals; no allocation allowed) -------------
__device__ float g_bufA[(size_t)N_NODES * 128];
__device__ float g_bufB[(size_t)N_NODES * 128];
__device__ float g_bufC[(size_t)N_NODES * 128];
__device__ int   g_cnt[N_NODES];
__device__ int   g_rowptr[N_NODES + 1];
__device__ int   g_fill[N_NODES];
__device__ int   g_srcs[N_EDGES];
__device__ float g_pooled[N_GRAPHS * 64];
__device__ int   g_ei64;   // 1 if edge_index buffer is int64, else int32
__device__ int   g_bt64;   // 1 if batch buffer is int64, else int32

// ---------------- dtype probe (JAX may silently demote int64 -> int32) -------
__global__ void k_detect(const void* ei, const void* batch) {
    if (threadIdx.x != 0 || blockIdx.x != 0) return;
    // edge_index: sample odd 32-bit words among the first 128 words.
    // int64 buffer: odd words are high words of values < 2^31 -> all 0.
    // int32 buffer: odd words are node indices, ~never all 0.
    const int* w = (const int*)ei;
    int s = 0;
    for (int i = 1; i < 128; i += 2) s |= w[i];
    g_ei64 = (s == 0) ? 1 : 0;
    // batch: sorted ascending, ends near N_GRAPHS-1. Probe odd words just
    // below word index N_NODES. int64: those are high words (0).
    // int32: late batch values (~127, nonzero).
    const int* b = (const int*)batch;
    int t = 0;
    for (int i = N_NODES - 63; i < N_NODES; i += 2) t |= b[i];
    g_bt64 = (t == 0) ? 1 : 0;
}

__device__ __forceinline__ int load_idx(const void* p, long long i, int is64) {
    return is64 ? (int)((const long long*)p)[i] : ((const int*)p)[i];
}

// ---------------- CSR build --------------------------------------------------
__global__ void k_zero() {
    int i = blockIdx.x * blockDim.x + threadIdx.x;
    if (i < N_NODES) g_cnt[i] = 0;
    if (i < N_GRAPHS * 64) g_pooled[i] = 0.f;
}

__global__ void k_hist(const void* __restrict__ ei) {
    int e = blockIdx.x * blockDim.x + threadIdx.x;
    int is64 = g_ei64;
    if (e < N_EDGES) atomicAdd(&g_cnt[load_idx(ei, (long long)N_EDGES + e, is64)], 1);
}

// single-block exclusive scan over g_cnt -> g_rowptr, g_fill (shuffle-based)
__global__ void k_scan() {
    __shared__ int warp_sums[32];
    __shared__ int s_carry;
    int tid = threadIdx.x, lane = tid & 31, wid = tid >> 5;
    if (tid == 0) s_carry = 0;
    __syncthreads();
    for (int base = 0; base < N_NODES; base += 1024) {
        int i = base + tid;
        int v = (i < N_NODES) ? g_cnt[i] : 0;
        int x = v;
#pragma unroll
        for (int off = 1; off < 32; off <<= 1) {
            int y = __shfl_up_sync(0xFFFFFFFFu, x, off);
            if (lane >= off) x += y;
        }
        if (lane == 31) warp_sums[wid] = x;
        __syncthreads();
        if (wid == 0) {
            int s = warp_sums[lane];
#pragma unroll
            for (int off = 1; off < 32; off <<= 1) {
                int y = __shfl_up_sync(0xFFFFFFFFu, s, off);
                if (lane >= off) s += y;
            }
            warp_sums[lane] = s;
        }
        __syncthreads();
        int excl = x - v + (wid ? warp_sums[wid - 1] : 0) + s_carry;
        if (i < N_NODES) { g_rowptr[i] = excl; g_fill[i] = excl; }
        __syncthreads();
        if (tid == 0) s_carry += warp_sums[31];
        __syncthreads();
    }
    if (threadIdx.x == 0) g_rowptr[N_NODES] = N_EDGES;
}

__global__ void k_fillcsr(const void* __restrict__ ei) {
    int e = blockIdx.x * blockDim.x + threadIdx.x;
    int is64 = g_ei64;
    if (e < N_EDGES) {
        int dst = load_idx(ei, (long long)N_EDGES + e, is64);
        int pos = atomicAdd(&g_fill[dst], 1);
        g_srcs[pos] = load_idx(ei, e, is64);
    }
}

// ---------------- 3xTF32 tensor-core GEMM ------------------------------------
// out[M,BN] = A[M,K] @ W[K,BN] (+bias)(+relu). BM=128, BK=32, warp tile 64x32.
__device__ __forceinline__ void tf32_split(float x, uint32_t& hi, uint32_t& lo) {
    uint32_t h;
    asm("cvt.rna.tf32.f32 %0, %1;" : "=r"(h) : "f"(x));
    float hf = __uint_as_float(h);
    asm("cvt.rna.tf32.f32 %0, %1;" : "=r"(lo) : "f"(x - hf));
    hi = h;
}

#define MMA_TF32(d, a, b)                                                     \
    asm volatile(                                                             \
        "mma.sync.aligned.m16n8k8.row.col.f32.tf32.tf32.f32 "                 \
        "{%0,%1,%2,%3}, {%4,%5,%6,%7}, {%8,%9}, {%0,%1,%2,%3};"               \
        : "+f"((d)[0]), "+f"((d)[1]), "+f"((d)[2]), "+f"((d)[3])              \
        : "r"((a)[0]), "r"((a)[1]), "r"((a)[2]), "r"((a)[3]),                 \
          "r"((b)[0]), "r"((b)[1]))

template <int BN, bool RELU, bool BIAS>
__global__ void __launch_bounds__(2 * (BN / 32) * 32)
k_gemm_tf32(const float* __restrict__ A, const float* __restrict__ W,
            const float* __restrict__ bias, float* __restrict__ out,
            int M, int K) {
    constexpr int BM = 128, BK = 32;
    constexpr int NWARP_N = BN / 32;
    constexpr int THREADS = 2 * NWARP_N * 32;
    constexpr int ASTR = BK + 4;   // 36: frag-load banks (36*g)%32=4g, conflict-free
    constexpr int BSTR = BN + 8;   // 136/72: frag-load banks (8*tig+g)%32, conflict-free

    __shared__ float Ah[BM][ASTR], Al[BM][ASTR];
    __shared__ float Bh[BK][BSTR], Bl[BK][BSTR];

    int tid = threadIdx.x;
    int warp = tid >> 5, lane = tid & 31;
    int wm = warp & 1;           // 0..1 over M
    int wn = warp >> 1;          // 0..NWARP_N-1 over N
    int g = lane >> 2, tig = lane & 3;
    int row0 = blockIdx.x * BM;

    float acc[4][4][4];
#pragma unroll
    for (int i = 0; i < 4; i++)
#pragma unroll
        for (int j = 0; j < 4; j++)
#pragma unroll
            for (int c = 0; c < 4; c++) acc[i][j][c] = 0.f;

    for (int k0 = 0; k0 < K; k0 += BK) {
        // load + split A tile: BM x BK (float4 granules)
#pragma unroll
        for (int i = tid; i < BM * BK / 4; i += THREADS) {
            int m = i / (BK / 4), c = i % (BK / 4);
            int r = row0 + m;
            if (r >= M) r = M - 1;
            float4 v = *(const float4*)&A[(size_t)r * K + k0 + c * 4];
            uint32_t h, l;
            tf32_split(v.x, h, l); Ah[m][c * 4 + 0] = __uint_as_float(h); Al[m][c * 4 + 0] = __uint_as_float(l);
            tf32_split(v.y, h, l); Ah[m][c * 4 + 1] = __uint_as_float(h); Al[m][c * 4 + 1] = __uint_as_float(l);
            tf32_split(v.z, h, l); Ah[m][c * 4 + 2] = __uint_as_float(h); Al[m][c * 4 + 2] = __uint_as_float(l);
            tf32_split(v.w, h, l); Ah[m][c * 4 + 3] = __uint_as_float(h); Al[m][c * 4 + 3] = __uint_as_float(l);
        }
        // load + split B tile: BK x BN
#pragma unroll
        for (int i = tid; i < BK * BN / 4; i += THREADS) {
            int k = i / (BN / 4), c = i % (BN / 4);
            float4 v = *(const float4*)&W[(size_t)(k0 + k) * BN + c * 4];
            uint32_t h, l;
            tf32_split(v.x, h, l); Bh[k][c * 4 + 0] = __uint_as_float(h); Bl[k][c * 4 + 0] = __uint_as_float(l);
            tf32_split(v.y, h, l); Bh[k][c * 4 + 1] = __uint_as_float(h); Bl[k][c * 4 + 1] = __uint_as_float(l);
            tf32_split(v.z, h, l); Bh[k][c * 4 + 2] = __uint_as_float(h); Bl[k][c * 4 + 2] = __uint_as_float(l);
            tf32_split(v.w, h, l); Bh[k][c * 4 + 3] = __uint_as_float(h); Bl[k][c * 4 + 3] = __uint_as_float(l);
        }
        __syncthreads();

#pragma unroll
        for (int ks = 0; ks < BK / 8; ks++) {
            int kb = ks * 8;
            uint32_t ah[4][4], al[4][4];
#pragma unroll
            for (int ma = 0; ma < 4; ma++) {
                int r = wm * 64 + ma * 16;
                ah[ma][0] = __float_as_uint(Ah[r + g    ][kb + tig    ]);
                ah[ma][1] = __float_as_uint(Ah[r + g + 8][kb + tig    ]);
                ah[ma][2] = __float_as_uint(Ah[r + g    ][kb + tig + 4]);
                ah[ma][3] = __float_as_uint(Ah[r + g + 8][kb + tig + 4]);
                al[ma][0] = __float_as_uint(Al[r + g    ][kb + tig    ]);
                al[ma][1] = __float_as_uint(Al[r + g + 8][kb + tig    ]);
                al[ma][2] = __float_as_uint(Al[r + g    ][kb + tig + 4]);
                al[ma][3] = __float_as_uint(Al[r + g + 8][kb + tig + 4]);
            }
            uint32_t bh[4][2], bl[4][2];
#pragma unroll
            for (int na = 0; na < 4; na++) {
                int cc = wn * 32 + na * 8;
                bh[na][0] = __float_as_uint(Bh[kb + tig    ][cc + g]);
                bh[na][1] = __float_as_uint(Bh[kb + tig + 4][cc + g]);
                bl[na][0] = __float_as_uint(Bl[kb + tig    ][cc + g]);
                bl[na][1] = __float_as_uint(Bl[kb + tig + 4][cc + g]);
            }
#pragma unroll
            for (int ma = 0; ma < 4; ma++)
#pragma unroll
                for (int na = 0; na < 4; na++) {
                    MMA_TF32(acc[ma][na], ah[ma], bh[na]);
                    MMA_TF32(acc[ma][na], ah[ma], bl[na]);
                    MMA_TF32(acc[ma][na], al[ma], bh[na]);
                }
        }
        __syncthreads();
    }

    // epilogue
#pragma unroll
    for (int na = 0; na < 4; na++) {
        int col = wn * 32 + na * 8 + 2 * tig;
        float2 bv = make_float2(0.f, 0.f);
        if (BIAS) { bv.x = bias[col]; bv.y = bias[col + 1]; }
#pragma unroll
        for (int ma = 0; ma < 4; ma++) {
            int row = row0 + wm * 64 + ma * 16 + g;
            float2 v0 = make_float2(acc[ma][na][0] + bv.x, acc[ma][na][1] + bv.y);
            float2 v1 = make_float2(acc[ma][na][2] + bv.x, acc[ma][na][3] + bv.y);
            if (RELU) {
                v0.x = fmaxf(v0.x, 0.f); v0.y = fmaxf(v0.y, 0.f);
                v1.x = fmaxf(v1.x, 0.f); v1.y = fmaxf(v1.y, 0.f);
            }
            if (row < M)     *(float2*)&out[(size_t)row * BN + col]       = v0;
            if (row + 8 < M) *(float2*)&out[(size_t)(row + 8) * BN + col] = v1;
        }
    }
}

// -------- aggregation + BN + ReLU:  out = relu(BN((1+eps)*y[n] + sum_nbr y + ba))
// One warp per node; edge loop unrolled x4 for MLP (independent L2 gathers).
__global__ void k_agg(const float* __restrict__ y, float* __restrict__ out,
                      const float* __restrict__ eps, const float* __restrict__ ba,
                      const float* __restrict__ gam, const float* __restrict__ bet,
                      const float* __restrict__ mu, const float* __restrict__ var) {
    int warp = threadIdx.x >> 5;
    int lane = threadIdx.x & 31;
    int node = blockIdx.x * (blockDim.x >> 5) + warp;
    if (node >= N_NODES) return;

    float e1 = 1.0f + eps[0];
    const float4* y4 = (const float4*)y;   // 32 float4 per 128-wide row
    float4 acc = y4[(size_t)node * 32 + lane];
    acc.x *= e1; acc.y *= e1; acc.z *= e1; acc.w *= e1;

    int beg = g_rowptr[node], end = g_rowptr[node + 1];
    int t = beg;
    for (; t + 4 <= end; t += 4) {
        int s0 = g_srcs[t],     s1 = g_srcs[t + 1];
        int s2 = g_srcs[t + 2], s3 = g_srcs[t + 3];
        float4 u0 = y4[(size_t)s0 * 32 + lane];
        float4 u1 = y4[(size_t)s1 * 32 + lane];
        float4 u2 = y4[(size_t)s2 * 32 + lane];
        float4 u3 = y4[(size_t)s3 * 32 + lane];
        acc.x += (u0.x + u1.x) + (u2.x + u3.x);
        acc.y += (u0.y + u1.y) + (u2.y + u3.y);
        acc.z += (u0.z + u1.z) + (u2.z + u3.z);
        acc.w += (u0.w + u1.w) + (u2.w + u3.w);
    }
    for (; t < end; t++) {
        int s = g_srcs[t];
        float4 u = y4[(size_t)s * 32 + lane];
        acc.x += u.x; acc.y += u.y; acc.z += u.z; acc.w += u.w;
    }

    int f = lane * 4;
    float4 BA = *(const float4*)&ba[f];
    float4 G  = *(const float4*)&gam[f];
    float4 BE = *(const float4*)&bet[f];
    float4 MU = *(const float4*)&mu[f];
    float4 V  = *(const float4*)&var[f];

    float4 o;
    o.x = fmaxf((acc.x + BA.x - MU.x) * rsqrtf(V.x + 1e-5f) * G.x + BE.x, 0.f);
    o.y = fmaxf((acc.y + BA.y - MU.y) * rsqrtf(V.y + 1e-5f) * G.y + BE.y, 0.f);
    o.z = fmaxf((acc.z + BA.z - MU.z) * rsqrtf(V.z + 1e-5f) * G.z + BE.z, 0.f);
    o.w = fmaxf((acc.w + BA.w - MU.w) * rsqrtf(V.w + 1e-5f) * G.w + BE.w, 0.f);
    ((float4*)out)[(size_t)node * 32 + lane] = o;
}

// ---------------- pooling (batch is sorted: register-run accumulation) -------
__global__ void k_pool(const float* __restrict__ h, const void* __restrict__ batch) {
    int f = threadIdx.x & 63, s = threadIdx.x >> 6;   // 256 threads: 64 feats x 4 lanes
    int n0 = blockIdx.x * 1024;
    int nend = n0 + 1024; if (nend > N_NODES) nend = N_NODES;
    int is64 = g_bt64;
    float acc = 0.f;
    int cur = -1;
    for (int n = n0 + s; n < nend; n += 4) {
        int gid = load_idx(batch, n, is64);
        if (gid != cur) {
            if (cur >= 0) atomicAdd(&g_pooled[cur * 64 + f], acc);
            cur = gid; acc = 0.f;
        }
        acc += h[(size_t)n * 64 + f];
    }
    if (cur >= 0) atomicAdd(&g_pooled[cur * 64 + f], acc);
}

__global__ void k_cls(const float* __restrict__ wc, const float* __restrict__ bc,
                      float* __restrict__ out) {
    int t = threadIdx.x;
    if (t < N_GRAPHS * 2) {
        int gi = t >> 1, c = t & 1;
        float s = bc[c];
#pragma unroll
        for (int k = 0; k < 64; k++) s += g_pooled[gi * 64 + k] * wc[k * 2 + c];
        out[t] = s;
    }
}

// ---------------- orchestration ----------------------------------------------
extern "C" void kernel_launch(void* const* d_in, const int* in_sizes, int n_in,
                              void* d_out, int out_size) {
    const float* x     = (const float*)d_in[0];
    const void*  ei    = d_in[1];
    const void*  batch = d_in[2];
    const float *eps1 = (const float*)d_in[3],  *w1a = (const float*)d_in[4],
                *b1a  = (const float*)d_in[5],  *g1  = (const float*)d_in[6],
                *be1  = (const float*)d_in[7],  *m1  = (const float*)d_in[8],
                *v1   = (const float*)d_in[9],  *w1b = (const float*)d_in[10],
                *b1b  = (const float*)d_in[11];
    const float *eps2 = (const float*)d_in[12], *w2a = (const float*)d_in[13],
                *b2a  = (const float*)d_in[14], *g2  = (const float*)d_in[15],
                *be2  = (const float*)d_in[16], *m2  = (const float*)d_in[17],
                *v2   = (const float*)d_in[18], *w2b = (const float*)d_in[19],
                *b2b  = (const float*)d_in[20];
    const float *eps3 = (const float*)d_in[21], *w3a = (const float*)d_in[22],
                *b3a  = (const float*)d_in[23], *g3  = (const float*)d_in[24],
                *be3  = (const float*)d_in[25], *m3  = (const float*)d_in[26],
                *v3   = (const float*)d_in[27], *w3b = (const float*)d_in[28],
                *b3b  = (const float*)d_in[29];
    const float *wc = (const float*)d_in[30], *bc = (const float*)d_in[31];
    float* out = (float*)d_out;

    float *A, *B, *C;
    cudaGetSymbolAddress((void**)&A, g_bufA);
    cudaGetSymbolAddress((void**)&B, g_bufB);
    cudaGetSymbolAddress((void**)&C, g_bufC);

    const int M = N_NODES;
    const int GEMM_BLKS = (M + 127) / 128;

    k_detect<<<1, 32>>>(ei, batch);
    k_zero<<<(N_NODES + 255) / 256, 256>>>();
    k_hist<<<(N_EDGES + 255) / 256, 256>>>(ei);
    k_scan<<<1, 1024>>>();
    k_fillcsr<<<(N_EDGES + 255) / 256, 256>>>(ei);

    // layer 1:  y1 = x @ w1a ; agg+bias+BN+relu ; @ w1b + b1b, relu
    k_gemm_tf32<128, false, false><<<GEMM_BLKS, 256>>>(x, w1a, nullptr, A, M, 384);
    k_agg<<<(N_NODES + 7) / 8, 256>>>(A, B, eps1, b1a, g1, be1, m1, v1);
    k_gemm_tf32<128, true, true><<<GEMM_BLKS, 256>>>(B, w1b, b1b, C, M, 128);

    // layer 2
    k_gemm_tf32<128, false, false><<<GEMM_BLKS, 256>>>(C, w2a, nullptr, A, M, 128);
    k_agg<<<(N_NODES + 7) / 8, 256>>>(A, B, eps2, b2a, g2, be2, m2, v2);
    k_gemm_tf32<128, true, true><<<GEMM_BLKS, 256>>>(B, w2b, b2b, C, M, 128);

    // layer 3 (second GEMM is 128 -> 64)
    k_gemm_tf32<128, false, false><<<GEMM_BLKS, 256>>>(C, w3a, nullptr, A, M, 128);
    k_agg<<<(N_NODES + 7) / 8, 256>>>(A, B, eps3, b3a, g3, be3, m3, v3);
    k_gemm_tf32<64, true, true><<<GEMM_BLKS, 128>>>(B, w3b, b3b, C, M, 128);

    // pool + classifier
    k_pool<<<(N_NODES + 1023) / 1024, 256>>>(C, batch);
    k_cls<<<1, 256>>>(wc, bc, out);
}

// round 7
// speedup vs baseline: 1.1500x; 1.1500x over previous
#include <cuda_runtime.h>
#include <cstdint>

#define N_NODES 100000
#define N_EDGES 800000
#define N_GRAPHS 128
#define SCAN_BLK 1024
#define SCAN_NBLK ((N_NODES + SCAN_BLK - 1) / SCAN_BLK)   // 98

// ---------------- scratch (device globals; no allocation allowed) -------------
__device__ float g_bufA[(size_t)N_NODES * 128];
__device__ float g_bufB[(size_t)N_NODES * 128];
__device__ float g_bufC[(size_t)N_NODES * 128];
__device__ int   g_cnt[N_NODES];
__device__ int   g_rowptr[N_NODES + 1];
__device__ int   g_fill[N_NODES];
__device__ int   g_srcs[N_EDGES];
__device__ float g_pooled[N_GRAPHS * 64];
__device__ int   g_part[128];       // per-block partial sums
__device__ int   g_partscan[128];   // exclusive scan of partials
__device__ int   g_ei64;   // 1 if edge_index buffer is int64, else int32
__device__ int   g_bt64;   // 1 if batch buffer is int64, else int32

__device__ __forceinline__ int load_idx(const void* p, long long i, int is64) {
    return is64 ? (int)((const long long*)p)[i] : ((const int*)p)[i];
}

// ---------------- zero + dtype detect (fused) ---------------------------------
// JAX may silently demote int64 -> int32; probe odd 32-bit words.
__global__ void k_zero(const void* ei, const void* batch) {
    int i = blockIdx.x * blockDim.x + threadIdx.x;
    if (i < N_NODES) g_cnt[i] = 0;
    if (i < N_GRAPHS * 64) g_pooled[i] = 0.f;
    if (blockIdx.x == 0 && threadIdx.x < 64) {
        int lane = threadIdx.x & 31;
        if (threadIdx.x < 32) {
            // edge_index head: odd words are int64 high words (0) or int32 data
            int w = ((const int*)ei)[2 * lane + 1];
            unsigned any = __ballot_sync(0xFFFFFFFFu, w != 0);
            if (lane == 0) g_ei64 = (any == 0) ? 1 : 0;
        } else {
            // batch tail: odd word indices in [N_NODES-63, N_NODES-1]
            int w = ((const int*)batch)[N_NODES - 63 + 2 * lane];
            unsigned any = __ballot_sync(0xFFFFFFFFu, w != 0);
            if (lane == 0) g_bt64 = (any == 0) ? 1 : 0;
        }
    }
}

// ---------------- CSR build --------------------------------------------------
__global__ void k_hist(const void* __restrict__ ei) {
    int e = blockIdx.x * blockDim.x + threadIdx.x;
    int is64 = g_ei64;
    if (e < N_EDGES) atomicAdd(&g_cnt[load_idx(ei, (long long)N_EDGES + e, is64)], 1);
}

// ---- 3-pass parallel exclusive scan of g_cnt -> g_rowptr, g_fill -------------
__global__ void k_scan_part() {
    __shared__ int ws[32];
    int i = blockIdx.x * SCAN_BLK + threadIdx.x;
    int lane = threadIdx.x & 31, wid = threadIdx.x >> 5;
    int v = (i < N_NODES) ? g_cnt[i] : 0;
#pragma unroll
    for (int off = 16; off >= 1; off >>= 1) v += __shfl_down_sync(0xFFFFFFFFu, v, off);
    if (lane == 0) ws[wid] = v;
    __syncthreads();
    if (wid == 0) {
        int s = ws[lane];
#pragma unroll
        for (int off = 16; off >= 1; off >>= 1) s += __shfl_down_sync(0xFFFFFFFFu, s, off);
        if (lane == 0) g_part[blockIdx.x] = s;
    }
}

__global__ void k_scan_top() {
    __shared__ int ws[4];
    int tid = threadIdx.x;                 // 128 threads
    int lane = tid & 31, wid = tid >> 5;
    int v = (tid < SCAN_NBLK) ? g_part[tid] : 0;
    int x = v;
#pragma unroll
    for (int off = 1; off < 32; off <<= 1) {
        int y = __shfl_up_sync(0xFFFFFFFFu, x, off);
        if (lane >= off) x += y;
    }
    if (lane == 31) ws[wid] = x;
    __syncthreads();
    if (wid == 0 && lane < 4) {
        int s = ws[lane];
#pragma unroll
        for (int off = 1; off < 4; off <<= 1) {
            int y = __shfl_up_sync(0xFu, s, off);
            if (lane >= off) s += y;
        }
        ws[lane] = s;
    }
    __syncthreads();
    int excl = x - v + (wid ? ws[wid - 1] : 0);
    if (tid < SCAN_NBLK) g_partscan[tid] = excl;
    if (tid == 0) g_rowptr[N_NODES] = N_EDGES;
}

__global__ void k_scan_apply() {
    __shared__ int ws[32];
    int i = blockIdx.x * SCAN_BLK + threadIdx.x;
    int lane = threadIdx.x & 31, wid = threadIdx.x >> 5;
    int v = (i < N_NODES) ? g_cnt[i] : 0;
    int x = v;
#pragma unroll
    for (int off = 1; off < 32; off <<= 1) {
        int y = __shfl_up_sync(0xFFFFFFFFu, x, off);
        if (lane >= off) x += y;
    }
    if (lane == 31) ws[wid] = x;
    __syncthreads();
    if (wid == 0) {
        int s = ws[lane];
#pragma unroll
        for (int off = 1; off < 32; off <<= 1) {
            int y = __shfl_up_sync(0xFFFFFFFFu, s, off);
            if (lane >= off) s += y;
        }
        ws[lane] = s;
    }
    __syncthreads();
    int excl = x - v + (wid ? ws[wid - 1] : 0) + g_partscan[blockIdx.x];
    if (i < N_NODES) { g_rowptr[i] = excl; g_fill[i] = excl; }
}

__global__ void k_fillcsr(const void* __restrict__ ei) {
    int e = blockIdx.x * blockDim.x + threadIdx.x;
    int is64 = g_ei64;
    if (e < N_EDGES) {
        int dst = load_idx(ei, (long long)N_EDGES + e, is64);
        int pos = atomicAdd(&g_fill[dst], 1);
        g_srcs[pos] = load_idx(ei, e, is64);
    }
}

// ---------------- 3xTF32 tensor-core GEMM (register-prefetch pipelined) ------
// out[M,BN] = A[M,K] @ W[K,BN] (+bias)(+relu). BM=128, BK=32, warp tile 64x32.
__device__ __forceinline__ void tf32_split(float x, uint32_t& hi, uint32_t& lo) {
    uint32_t h;
    asm("cvt.rna.tf32.f32 %0, %1;" : "=r"(h) : "f"(x));
    float hf = __uint_as_float(h);
    asm("cvt.rna.tf32.f32 %0, %1;" : "=r"(lo) : "f"(x - hf));
    hi = h;
}

#define MMA_TF32(d, a, b)                                                     \
    asm volatile(                                                             \
        "mma.sync.aligned.m16n8k8.row.col.f32.tf32.tf32.f32 "                 \
        "{%0,%1,%2,%3}, {%4,%5,%6,%7}, {%8,%9}, {%0,%1,%2,%3};"               \
        : "+f"((d)[0]), "+f"((d)[1]), "+f"((d)[2]), "+f"((d)[3])              \
        : "r"((a)[0]), "r"((a)[1]), "r"((a)[2]), "r"((a)[3]),                 \
          "r"((b)[0]), "r"((b)[1]))

template <int BN, bool RELU, bool BIAS>
__global__ void __launch_bounds__(2 * (BN / 32) * 32)
k_gemm_tf32(const float* __restrict__ A, const float* __restrict__ W,
            const float* __restrict__ bias, float* __restrict__ out,
            int M, int K) {
    constexpr int BM = 128, BK = 32;
    constexpr int NWARP_N = BN / 32;
    constexpr int THREADS = 2 * NWARP_N * 32;
    constexpr int ASTR = BK + 4;   // 36: frag-load banks (36*g)%32=4g, conflict-free
    constexpr int BSTR = BN + 8;   // 136/72: frag-load banks (8*tig+g)%32, conflict-free
    constexpr int NA = (BM * BK / 4) / THREADS;   // float4 granules per thread (A)
    constexpr int NB = (BK * BN / 4) / THREADS;   // float4 granules per thread (B)

    __shared__ float Ah[BM][ASTR], Al[BM][ASTR];
    __shared__ float Bh[BK][BSTR], Bl[BK][BSTR];

    int tid = threadIdx.x;
    int warp = tid >> 5, lane = tid & 31;
    int wm = warp & 1;           // 0..1 over M
    int wn = warp >> 1;          // 0..NWARP_N-1 over N
    int g = lane >> 2, tig = lane & 3;
    int row0 = blockIdx.x * BM;

    float acc[4][4][4];
#pragma unroll
    for (int i = 0; i < 4; i++)
#pragma unroll
        for (int j = 0; j < 4; j++)
#pragma unroll
            for (int c = 0; c < 4; c++) acc[i][j][c] = 0.f;

    float4 ra[NA], rb[NB];
    // prologue: load tile k0=0 into registers
#pragma unroll
    for (int j = 0; j < NA; j++) {
        int i = tid + j * THREADS;
        int m = i / (BK / 4), c = i % (BK / 4);
        int r = row0 + m; if (r >= M) r = M - 1;
        ra[j] = *(const float4*)&A[(size_t)r * K + c * 4];
    }
#pragma unroll
    for (int j = 0; j < NB; j++) {
        int i = tid + j * THREADS;
        int k = i / (BN / 4), c = i % (BN / 4);
        rb[j] = *(const float4*)&W[(size_t)k * BN + c * 4];
    }

    for (int k0 = 0; k0 < K; k0 += BK) {
        // split registers -> smem (no memory latency in this phase)
#pragma unroll
        for (int j = 0; j < NA; j++) {
            int i = tid + j * THREADS;
            int m = i / (BK / 4), c = i % (BK / 4);
            uint32_t h, l;
            tf32_split(ra[j].x, h, l); Ah[m][c * 4 + 0] = __uint_as_float(h); Al[m][c * 4 + 0] = __uint_as_float(l);
            tf32_split(ra[j].y, h, l); Ah[m][c * 4 + 1] = __uint_as_float(h); Al[m][c * 4 + 1] = __uint_as_float(l);
            tf32_split(ra[j].z, h, l); Ah[m][c * 4 + 2] = __uint_as_float(h); Al[m][c * 4 + 2] = __uint_as_float(l);
            tf32_split(ra[j].w, h, l); Ah[m][c * 4 + 3] = __uint_as_float(h); Al[m][c * 4 + 3] = __uint_as_float(l);
        }
#pragma unroll
        for (int j = 0; j < NB; j++) {
            int i = tid + j * THREADS;
            int k = i / (BN / 4), c = i % (BN / 4);
            uint32_t h, l;
            tf32_split(rb[j].x, h, l); Bh[k][c * 4 + 0] = __uint_as_float(h); Bl[k][c * 4 + 0] = __uint_as_float(l);
            tf32_split(rb[j].y, h, l); Bh[k][c * 4 + 1] = __uint_as_float(h); Bl[k][c * 4 + 1] = __uint_as_float(l);
            tf32_split(rb[j].z, h, l); Bh[k][c * 4 + 2] = __uint_as_float(h); Bl[k][c * 4 + 2] = __uint_as_float(l);
            tf32_split(rb[j].w, h, l); Bh[k][c * 4 + 3] = __uint_as_float(h); Bl[k][c * 4 + 3] = __uint_as_float(l);
        }
        __syncthreads();

        // prefetch next tile (loads overlap the MMA phase below)
        int kn = k0 + BK;
        if (kn < K) {
#pragma unroll
            for (int j = 0; j < NA; j++) {
                int i = tid + j * THREADS;
                int m = i / (BK / 4), c = i % (BK / 4);
                int r = row0 + m; if (r >= M) r = M - 1;
                ra[j] = *(const float4*)&A[(size_t)r * K + kn + c * 4];
            }
#pragma unroll
            for (int j = 0; j < NB; j++) {
                int i = tid + j * THREADS;
                int k = i / (BN / 4), c = i % (BN / 4);
                rb[j] = *(const float4*)&W[(size_t)(kn + k) * BN + c * 4];
            }
        }

#pragma unroll
        for (int ks = 0; ks < BK / 8; ks++) {
            int kb = ks * 8;
            uint32_t ah[4][4], al[4][4];
#pragma unroll
            for (int ma = 0; ma < 4; ma++) {
                int r = wm * 64 + ma * 16;
                ah[ma][0] = __float_as_uint(Ah[r + g    ][kb + tig    ]);
                ah[ma][1] = __float_as_uint(Ah[r + g + 8][kb + tig    ]);
                ah[ma][2] = __float_as_uint(Ah[r + g    ][kb + tig + 4]);
                ah[ma][3] = __float_as_uint(Ah[r + g + 8][kb + tig + 4]);
                al[ma][0] = __float_as_uint(Al[r + g    ][kb + tig    ]);
                al[ma][1] = __float_as_uint(Al[r + g + 8][kb + tig    ]);
                al[ma][2] = __float_as_uint(Al[r + g    ][kb + tig + 4]);
                al[ma][3] = __float_as_uint(Al[r + g + 8][kb + tig + 4]);
            }
            uint32_t bh[4][2], bl[4][2];
#pragma unroll
            for (int na = 0; na < 4; na++) {
                int cc = wn * 32 + na * 8;
                bh[na][0] = __float_as_uint(Bh[kb + tig    ][cc + g]);
                bh[na][1] = __float_as_uint(Bh[kb + tig + 4][cc + g]);
                bl[na][0] = __float_as_uint(Bl[kb + tig    ][cc + g]);
                bl[na][1] = __float_as_uint(Bl[kb + tig + 4][cc + g]);
            }
#pragma unroll
            for (int ma = 0; ma < 4; ma++)
#pragma unroll
                for (int na = 0; na < 4; na++) {
                    MMA_TF32(acc[ma][na], ah[ma], bh[na]);
                    MMA_TF32(acc[ma][na], ah[ma], bl[na]);
                    MMA_TF32(acc[ma][na], al[ma], bh[na]);
                }
        }
        __syncthreads();
    }

    // epilogue
#pragma unroll
    for (int na = 0; na < 4; na++) {
        int col = wn * 32 + na * 8 + 2 * tig;
        float2 bv = make_float2(0.f, 0.f);
        if (BIAS) { bv.x = bias[col]; bv.y = bias[col + 1]; }
#pragma unroll
        for (int ma = 0; ma < 4; ma++) {
            int row = row0 + wm * 64 + ma * 16 + g;
            float2 v0 = make_float2(acc[ma][na][0] + bv.x, acc[ma][na][1] + bv.y);
            float2 v1 = make_float2(acc[ma][na][2] + bv.x, acc[ma][na][3] + bv.y);
            if (RELU) {
                v0.x = fmaxf(v0.x, 0.f); v0.y = fmaxf(v0.y, 0.f);
                v1.x = fmaxf(v1.x, 0.f); v1.y = fmaxf(v1.y, 0.f);
            }
            if (row < M)     *(float2*)&out[(size_t)row * BN + col]       = v0;
            if (row + 8 < M) *(float2*)&out[(size_t)(row + 8) * BN + col] = v1;
        }
    }
}

// -------- aggregation + BN + ReLU:  out = relu(BN((1+eps)*y[n] + sum_nbr y + ba))
// One warp per node; edge loop unrolled x4 for MLP (independent L2 gathers).
__global__ void k_agg(const float* __restrict__ y, float* __restrict__ out,
                      const float* __restrict__ eps, const float* __restrict__ ba,
                      const float* __restrict__ gam, const float* __restrict__ bet,
                      const float* __restrict__ mu, const float* __restrict__ var) {
    int warp = threadIdx.x >> 5;
    int lane = threadIdx.x & 31;
    int node = blockIdx.x * (blockDim.x >> 5) + warp;
    if (node >= N_NODES) return;

    float e1 = 1.0f + eps[0];
    const float4* y4 = (const float4*)y;   // 32 float4 per 128-wide row
    float4 acc = y4[(size_t)node * 32 + lane];
    acc.x *= e1; acc.y *= e1; acc.z *= e1; acc.w *= e1;

    int beg = g_rowptr[node], end = g_rowptr[node + 1];
    int t = beg;
    for (; t + 4 <= end; t += 4) {
        int s0 = g_srcs[t],     s1 = g_srcs[t + 1];
        int s2 = g_srcs[t + 2], s3 = g_srcs[t + 3];
        float4 u0 = y4[(size_t)s0 * 32 + lane];
        float4 u1 = y4[(size_t)s1 * 32 + lane];
        float4 u2 = y4[(size_t)s2 * 32 + lane];
        float4 u3 = y4[(size_t)s3 * 32 + lane];
        acc.x += (u0.x + u1.x) + (u2.x + u3.x);
        acc.y += (u0.y + u1.y) + (u2.y + u3.y);
        acc.z += (u0.z + u1.z) + (u2.z + u3.z);
        acc.w += (u0.w + u1.w) + (u2.w + u3.w);
    }
    for (; t < end; t++) {
        int s = g_srcs[t];
        float4 u = y4[(size_t)s * 32 + lane];
        acc.x += u.x; acc.y += u.y; acc.z += u.z; acc.w += u.w;
    }

    int f = lane * 4;
    float4 BA = *(const float4*)&ba[f];
    float4 G  = *(const float4*)&gam[f];
    float4 BE = *(const float4*)&bet[f];
    float4 MU = *(const float4*)&mu[f];
    float4 V  = *(const float4*)&var[f];

    float4 o;
    o.x = fmaxf((acc.x + BA.x - MU.x) * rsqrtf(V.x + 1e-5f) * G.x + BE.x, 0.f);
    o.y = fmaxf((acc.y + BA.y - MU.y) * rsqrtf(V.y + 1e-5f) * G.y + BE.y, 0.f);
    o.z = fmaxf((acc.z + BA.z - MU.z) * rsqrtf(V.z + 1e-5f) * G.z + BE.z, 0.f);
    o.w = fmaxf((acc.w + BA.w - MU.w) * rsqrtf(V.w + 1e-5f) * G.w + BE.w, 0.f);
    ((float4*)out)[(size_t)node * 32 + lane] = o;
}

// ---------------- pooling (batch is sorted: register-run accumulation) -------
__global__ void k_pool(const float* __restrict__ h, const void* __restrict__ batch) {
    int f = threadIdx.x & 63, s = threadIdx.x >> 6;   // 256 threads: 64 feats x 4 lanes
    int n0 = blockIdx.x * 1024;
    int nend = n0 + 1024; if (nend > N_NODES) nend = N_NODES;
    int is64 = g_bt64;
    float acc = 0.f;
    int cur = -1;
    for (int n = n0 + s; n < nend; n += 4) {
        int gid = load_idx(batch, n, is64);
        if (gid != cur) {
            if (cur >= 0) atomicAdd(&g_pooled[cur * 64 + f], acc);
            cur = gid; acc = 0.f;
        }
        acc += h[(size_t)n * 64 + f];
    }
    if (cur >= 0) atomicAdd(&g_pooled[cur * 64 + f], acc);
}

__global__ void k_cls(const float* __restrict__ wc, const float* __restrict__ bc,
                      float* __restrict__ out) {
    int t = threadIdx.x;
    if (t < N_GRAPHS * 2) {
        int gi = t >> 1, c = t & 1;
        float s = bc[c];
#pragma unroll
        for (int k = 0; k < 64; k++) s += g_pooled[gi * 64 + k] * wc[k * 2 + c];
        out[t] = s;
    }
}

// ---------------- orchestration ----------------------------------------------
extern "C" void kernel_launch(void* const* d_in, const int* in_sizes, int n_in,
                              void* d_out, int out_size) {
    const float* x     = (const float*)d_in[0];
    const void*  ei    = d_in[1];
    const void*  batch = d_in[2];
    const float *eps1 = (const float*)d_in[3],  *w1a = (const float*)d_in[4],
                *b1a  = (const float*)d_in[5],  *g1  = (const float*)d_in[6],
                *be1  = (const float*)d_in[7],  *m1  = (const float*)d_in[8],
                *v1   = (const float*)d_in[9],  *w1b = (const float*)d_in[10],
                *b1b  = (const float*)d_in[11];
    const float *eps2 = (const float*)d_in[12], *w2a = (const float*)d_in[13],
                *b2a  = (const float*)d_in[14], *g2  = (const float*)d_in[15],
                *be2  = (const float*)d_in[16], *m2  = (const float*)d_in[17],
                *v2   = (const float*)d_in[18], *w2b = (const float*)d_in[19],
                *b2b  = (const float*)d_in[20];
    const float *eps3 = (const float*)d_in[21], *w3a = (const float*)d_in[22],
                *b3a  = (const float*)d_in[23], *g3  = (const float*)d_in[24],
                *be3  = (const float*)d_in[25], *m3  = (const float*)d_in[26],
                *v3   = (const float*)d_in[27], *w3b = (const float*)d_in[28],
                *b3b  = (const float*)d_in[29];
    const float *wc = (const float*)d_in[30], *bc = (const float*)d_in[31];
    float* out = (float*)d_out;

    float *A, *B, *C;
    cudaGetSymbolAddress((void**)&A, g_bufA);
    cudaGetSymbolAddress((void**)&B, g_bufB);
    cudaGetSymbolAddress((void**)&C, g_bufC);

    const int M = N_NODES;
    const int GEMM_BLKS = (M + 127) / 128;

    // CSR build, parallel scan. gemm1 (CSR-independent) is placed at launch
    // slot 6 so ncu (-s 5 -c 1) profiles it.
    k_zero<<<(N_NODES + 255) / 256, 256>>>(ei, batch);            // 1
    k_hist<<<(N_EDGES + 255) / 256, 256>>>(ei);                   // 2
    k_scan_part<<<SCAN_NBLK, SCAN_BLK>>>();                       // 3
    k_scan_top<<<1, 128>>>();                                     // 4
    k_scan_apply<<<SCAN_NBLK, SCAN_BLK>>>();                      // 5
    k_gemm_tf32<128, false, false><<<GEMM_BLKS, 256>>>(x, w1a, nullptr, A, M, 384); // 6
    k_fillcsr<<<(N_EDGES + 255) / 256, 256>>>(ei);                // 7

    // layer 1 rest
    k_agg<<<(N_NODES + 7) / 8, 256>>>(A, B, eps1, b1a, g1, be1, m1, v1);
    k_gemm_tf32<128, true, true><<<GEMM_BLKS, 256>>>(B, w1b, b1b, C, M, 128);

    // layer 2
    k_gemm_tf32<128, false, false><<<GEMM_BLKS, 256>>>(C, w2a, nullptr, A, M, 128);
    k_agg<<<(N_NODES + 7) / 8, 256>>>(A, B, eps2, b2a, g2, be2, m2, v2);
    k_gemm_tf32<128, true, true><<<GEMM_BLKS, 256>>>(B, w2b, b2b, C, M, 128);

    // layer 3 (second GEMM is 128 -> 64)
    k_gemm_tf32<128, false, false><<<GEMM_BLKS, 256>>>(C, w3a, nullptr, A, M, 128);
    k_agg<<<(N_NODES + 7) / 8, 256>>>(A, B, eps3, b3a, g3, be3, m3, v3);
    k_gemm_tf32<64, true, true><<<GEMM_BLKS, 128>>>(B, w3b, b3b, C, M, 128);

    // pool + classifier
    k_pool<<<(N_NODES + 1023) / 1024, 256>>>(C, batch);
    k_cls<<<1, 256>>>(wc, bc, out);
}